// round 8
// baseline (speedup 1.0000x reference)
#include <cuda_runtime.h>

#define T     4096
#define NTH   160
#define C     16
#define W2I   132         // input-buffer pair-row width (8 rows x 132 = 1056 pairs)
#define W2R   130         // R1 buffer width (8 x 130 = 1040 pairs)
#define BUFI  (8 * W2I)
#define BUFR  (8 * W2R)
#define SMEM_BYTES ((8 * BUFI + BUFR) * 8)   // 2 sets x 4 inputs + R1 = 75904 B

typedef unsigned long long u64;

// db4 synthesis filters pre-scaled by 0.5
#define L0c ( 0.5f *  0.23037781330885523f)
#define L1c ( 0.5f *  0.7148465705525415f)
#define L2c ( 0.5f *  0.6308807679295904f)
#define L3c ( 0.5f * -0.02798376941698385f)
#define L4c ( 0.5f * -0.18703481171888114f)
#define L5c ( 0.5f *  0.030841381835986965f)
#define L6c ( 0.5f *  0.032883011666982945f)
#define L7c ( 0.5f * -0.010597401784997278f)
// rec_hi[k] = (-1)^k * rec_lo[7-k]
#define H0c ( L7c)
#define H1c (-L6c)
#define H2c ( L5c)
#define H3c (-L4c)
#define H4c ( L3c)
#define H5c (-L2c)
#define H6c ( L1c)
#define H7c (-L0c)

__constant__ float2 CL2[8] = {
    {L0c,L0c},{L1c,L1c},{L2c,L2c},{L3c,L3c},{L4c,L4c},{L5c,L5c},{L6c,L6c},{L7c,L7c}};
__constant__ float2 CH2[8] = {
    {H0c,H0c},{H1c,H1c},{H2c,H2c},{H3c,H3c},{H4c,H4c},{H5c,H5c},{H6c,H6c},{H7c,H7c}};

__device__ __forceinline__ void fma2(u64& d, u64 c, u64 v) {
    asm("fma.rn.f32x2 %0, %1, %2, %0;" : "+l"(d) : "l"(c), "l"(v));
}
__device__ __forceinline__ unsigned s2u(const void* p) {
    return (unsigned)__cvta_generic_to_shared(p);
}

// Async-stage one array (origin sample o, even, possibly negative) into an
// input buffer: pair p -> phys64 (p&7)*W2I + (p>>3), via 8-byte cp.async
// straight global->shared (no registers, no STS).
__device__ __forceinline__ void stage_async(u64* __restrict__ buf,
                                            const float* __restrict__ g,
                                            int o, int tid) {
    unsigned sb = s2u(buf);
#pragma unroll
    for (int i = 0; i < 7; ++i) {
        int p = tid + i * NTH;
        if (p < BUFI) {
            int si = (o + 2 * p) & (T - 1);          // even -> 8B-aligned, no cross
            unsigned d = sb + ((((p & 7) * W2I) + (p >> 3)) << 3);
            asm volatile("cp.async.ca.shared.global [%0], [%1], 8;"
                         :: "r"(d), "l"(g + si));
        }
    }
}

// Even-dilation pass: reads pairs 8t+q (q=0..QMAX); acc pair kk gets tap m
// from q = kk + (D*(3-m)+OFF)/2.   (verified-passing R7 template, W2 added)
template <int D, int OFF, int QMAX, int W2>
__device__ __forceinline__ void pass_even(const u64* __restrict__ buf, u64* acc,
                                          const float2* __restrict__ coef, int t) {
    u64 c[8];
    const u64* cu = (const u64*)coef;
#pragma unroll
    for (int m = 0; m < 8; ++m) c[m] = cu[m];
    const u64* p = buf + t;
#pragma unroll
    for (int q = 0; q <= QMAX; ++q) {
        u64 v = p[(q & 7) * W2 + (q >> 3)];
#pragma unroll
        for (int m = 0; m < 8; ++m) {
            const int kk = q - (D * (3 - m) + OFF) / 2;
            if (kk >= 0 && kk < 8) fma2(acc[kk], c[m], v);
        }
    }
}

// D=1 scalar pass (OFF=8): pairs q=2..13, halves consumed directly, FFMA-imm.
template <int W2>
__device__ __forceinline__ void pass_d1(const u64* __restrict__ buf,
                                        float* acc, const float* cf, int t) {
    const u64* p = buf + t;
#pragma unroll
    for (int q = 2; q <= 13; ++q) {
        u64 vv = p[(q & 7) * W2 + (q >> 3)];
        float2 v = *(float2*)&vv;
#pragma unroll
        for (int m = 0; m < 8; ++m) {
            {   const int j = 2 * q - 11 + m;
                if (j >= 0 && j < C) acc[j] = fmaf(cf[m], v.x, acc[j]); }
            {   const int j = 2 * q - 10 + m;
                if (j >= 0 && j < C) acc[j] = fmaf(cf[m], v.y, acc[j]); }
        }
    }
}

// One chunk: A=cA3, B=cD3, Cc=cD2, E=cD1 (all staged); R1 scratch; R2 -> A.
__device__ __forceinline__ void compute_chunk(u64* A, u64* B, u64* Cc, u64* E,
                                              u64* R1, float* __restrict__ orow,
                                              int S, int tid) {
    if (tid < 130) {                       // Level 1 (d=4): A,B -> R1 (origin S-16)
        u64 acc[8];
#pragma unroll
        for (int k = 0; k < 8; ++k) acc[k] = 0ULL;
        pass_even<4, 16, 21, W2I>(A, acc, CL2, tid);
        pass_even<4, 16, 21, W2I>(B, acc, CH2, tid);
        u64* p = R1 + tid;
#pragma unroll
        for (int k = 0; k < 8; ++k) p[k * W2R] = acc[k];
    }
    __syncthreads();
    if (tid < 129) {                       // Level 2 (d=2): R1,Cc -> R2 in A (origin S-8)
        u64 acc[8];
#pragma unroll
        for (int k = 0; k < 8; ++k) acc[k] = 0ULL;
        pass_even<2, 8, 14, W2R>(R1, acc, CL2, tid);
        pass_even<2, 8, 14, W2I>(Cc, acc, CH2, tid);
        u64* p = A + tid;
#pragma unroll
        for (int k = 0; k < 8; ++k) p[k * W2I] = acc[k];
    }
    __syncthreads();
    if (tid < 128) {                       // Level 3 (d=1): R2(A), cD1(E) -> global
        const float CFL[8] = {L0c,L1c,L2c,L3c,L4c,L5c,L6c,L7c};
        const float CFH[8] = {H0c,H1c,H2c,H3c,H4c,H5c,H6c,H7c};
        float acc[C];
#pragma unroll
        for (int j = 0; j < C; ++j) acc[j] = 0.0f;
        pass_d1<W2I>(A, acc, CFL, tid);
        pass_d1<W2I>(E, acc, CFH, tid);
        float4* o = (float4*)(orow + S + tid * C);
#pragma unroll
        for (int q = 0; q < 4; ++q)
            o[q] = make_float4(acc[4 * q + 0], acc[4 * q + 1],
                               acc[4 * q + 2], acc[4 * q + 3]);
    }
}

extern __shared__ u64 dsm[];

__global__ void __launch_bounds__(NTH, 3)
iswt_kernel(const float* __restrict__ x, float* __restrict__ out) {
    const int tid = threadIdx.x;
    const int bn  = blockIdx.x;               // row in [0, 2048); 2 chunks per CTA
    const float* g = x + (size_t)bn * 4 * T;  // cA3 | cD3 | cD2 | cD1
    float* orow    = out + (size_t)bn * T;

    u64* R1 = dsm + 8 * BUFI;

    // Issue ALL loads for both chunks up-front as two cp.async groups.
#pragma unroll
    for (int s = 0; s < 2; ++s) {
        const int S = s << 11;
        u64* base = dsm + s * 4 * BUFI;
        stage_async(base + 0 * BUFI, g + 0 * T, S - 32, tid);   // cA3
        stage_async(base + 1 * BUFI, g + 1 * T, S - 32, tid);   // cD3
        stage_async(base + 2 * BUFI, g + 2 * T, S - 16, tid);   // cD2
        stage_async(base + 3 * BUFI, g + 3 * T, S - 8,  tid);   // cD1
        asm volatile("cp.async.commit_group;");
    }

    // Chunk 0: wait for group 0 only (group 1 still streaming during compute)
    asm volatile("cp.async.wait_group %0;" :: "n"(1));
    __syncthreads();
    compute_chunk(dsm + 0 * BUFI, dsm + 1 * BUFI, dsm + 2 * BUFI, dsm + 3 * BUFI,
                  R1, orow, 0, tid);

    // Chunk 1
    asm volatile("cp.async.wait_group %0;" :: "n"(0));
    __syncthreads();
    compute_chunk(dsm + 4 * BUFI, dsm + 5 * BUFI, dsm + 6 * BUFI, dsm + 7 * BUFI,
                  R1, orow, 2048, tid);
}

extern "C" void kernel_launch(void* const* d_in, const int* in_sizes, int n_in,
                              void* d_out, int out_size) {
    const float* x = (const float*)d_in[0];
    float* out = (float*)d_out;
    cudaFuncSetAttribute(iswt_kernel,
                         cudaFuncAttributeMaxDynamicSharedMemorySize, SMEM_BYTES);
    iswt_kernel<<<2048, NTH, SMEM_BYTES>>>(x, out);
}

// round 9
// speedup vs baseline: 1.2305x; 1.2305x over previous
#include <cuda_runtime.h>

#define T     4096
#define TQ    1024        // float4s per array
#define NTH   160
#define C     16
#define W2    146         // pair-row width (64-bit units)
#define BUFP  (8 * W2)    // 1168 pairs per buffer
#define NSTG  528         // float4s staged per array (pairs 0..1055)

typedef unsigned long long u64;

// db4 synthesis filters pre-scaled by 0.5 (the per-level factor)
#define L0c ( 0.5f *  0.23037781330885523f)
#define L1c ( 0.5f *  0.7148465705525415f)
#define L2c ( 0.5f *  0.6308807679295904f)
#define L3c ( 0.5f * -0.02798376941698385f)
#define L4c ( 0.5f * -0.18703481171888114f)
#define L5c ( 0.5f *  0.030841381835986965f)
#define L6c ( 0.5f *  0.032883011666982945f)
#define L7c ( 0.5f * -0.010597401784997278f)
// rec_hi[k] = (-1)^k * rec_lo[7-k]  ->  even k: +L[7-k], odd k: -L[7-k]
#define H0c ( L7c)
#define H1c (-L6c)
#define H2c ( L5c)
#define H3c (-L4c)
#define H4c ( L3c)
#define H5c (-L2c)
#define H6c ( L1c)
#define H7c (-L0c)

// Packed (x == y) coefficient pairs for FFMA2, loaded as LDC.64 (no movs)
__constant__ float2 CL2[8] = {
    {L0c,L0c},{L1c,L1c},{L2c,L2c},{L3c,L3c},{L4c,L4c},{L5c,L5c},{L6c,L6c},{L7c,L7c}};
__constant__ float2 CH2[8] = {
    {H0c,H0c},{H1c,H1c},{H2c,H2c},{H3c,H3c},{H4c,H4c},{H5c,H5c},{H6c,H6c},{H7c,H7c}};

__device__ __forceinline__ void fma2(u64& d, u64 c, u64 v) {
    asm("fma.rn.f32x2 %0, %1, %2, %0;" : "+l"(d) : "l"(c), "l"(v));
}

// --- staging split into prefetch (LDG -> regs) and commit (regs -> smem) ---
struct Pref { float4 v[4]; };

__device__ __forceinline__ void prefetch(Pref& p, const float4* __restrict__ g4,
                                         int f4base, int tid) {
#pragma unroll
    for (int i = 0; i < 4; ++i) {
        int idx = tid + i * NTH;
        p.v[i] = (idx < NSTG) ? __ldg(&g4[(f4base + idx) & (TQ - 1)])
                              : make_float4(0.f, 0.f, 0.f, 0.f);
    }
}

__device__ __forceinline__ void commit(u64* __restrict__ s, const Pref& p, int tid) {
#pragma unroll
    for (int i = 0; i < 4; ++i) {
        int idx = tid + i * NTH;
        if (idx < NSTG) {
            int r = 2 * (idx & 3);
            int q = idx >> 2;
            *(float2*)(s + (r + 0) * W2 + q) = make_float2(p.v[i].x, p.v[i].y);
            *(float2*)(s + (r + 1) * W2 + q) = make_float2(p.v[i].z, p.v[i].w);
        }
    }
}

__device__ __forceinline__ void stage(u64* __restrict__ s,
                                      const float4* __restrict__ g4,
                                      int f4base, int tid) {
    Pref p; prefetch(p, g4, f4base, tid); commit(s, p, tid);
}

// Even-dilation pass (all tap shifts even): stream aligned pairs q = 0..QMAX.
// acc pair kk gets tap m from pair q = kk + (D*(3-m)+OFF)/2.
template <int D, int OFF, int QMAX>
__device__ __forceinline__ void pass_even(const u64* __restrict__ buf, u64* acc,
                                          const float2* __restrict__ coef, int t) {
    u64 c[8];
    const u64* cu = (const u64*)coef;          // LDC.64, no register packing
#pragma unroll
    for (int m = 0; m < 8; ++m) c[m] = cu[m];
    const u64* p = buf + t;
#pragma unroll
    for (int q = 0; q <= QMAX; ++q) {
        u64 v = p[(q & 7) * W2 + (q >> 3)];
#pragma unroll
        for (int m = 0; m < 8; ++m) {
            const int kk = q - (D * (3 - m) + OFF) / 2;
            if (kk >= 0 && kk < 8) fma2(acc[kk], c[m], v);
        }
    }
}

// D=1 scalar pass (OFF=8): acc[j] += coef[m] * buf[li], li = j + 11 - m.
// Stream pairs q=2..13 (li = 2q, 2q+1); halves consumed directly, FFMA-imm.
__device__ __forceinline__ void pass_d1(const u64* __restrict__ buf,
                                        float* acc, const float* cf, int t) {
    const u64* p = buf + t;
#pragma unroll
    for (int q = 2; q <= 13; ++q) {
        u64 vv = p[(q & 7) * W2 + (q >> 3)];
        float2 v = *(float2*)&vv;
#pragma unroll
        for (int m = 0; m < 8; ++m) {
            {   // li = 2q   -> j = 2q - 11 + m
                const int j = 2 * q - 11 + m;
                if (j >= 0 && j < C) acc[j] = fmaf(cf[m], v.x, acc[j]);
            }
            {   // li = 2q+1 -> j = 2q - 10 + m
                const int j = 2 * q - 10 + m;
                if (j >= 0 && j < C) acc[j] = fmaf(cf[m], v.y, acc[j]);
            }
        }
    }
}

__global__ void __launch_bounds__(NTH, 6)
iswt_kernel(const float* __restrict__ x, float* __restrict__ out) {
    __shared__ u64 sA[BUFP];   // cA3, then cD1
    __shared__ u64 sB[BUFP];   // cD3, then R2
    __shared__ u64 sC[BUFP];   // cD2
    __shared__ u64 sD[BUFP];   // R1

    const int bn  = blockIdx.x >> 1;          // row in [0, 2048)
    const int S   = (blockIdx.x & 1) << 11;   // chunk start: 0 or 2048
    const int tid = threadIdx.x;
    const float* g = x + (size_t)bn * 4 * T;  // cA3 | cD3 | cD2 | cD1
    const float4* g4 = (const float4*)g;

    const int o32 = (S - 32) >> 2;            // staging origins (float4 index)
    const int o16 = (S - 16) >> 2;
    const int o8  = (S - 8)  >> 2;

    // Issue ALL global loads up-front; only cA3/cD3 block (their STS).
    stage(sA, g4 + 0 * TQ, o32, tid);         // cA3  (origin S-32)
    stage(sB, g4 + 1 * TQ, o32, tid);         // cD3  (origin S-32)
    Pref pC; prefetch(pC, g4 + 2 * TQ, o16, tid);   // cD2 -> regs (in flight)
    Pref pE; prefetch(pE, g4 + 3 * TQ, o8,  tid);   // cD1 -> regs (in flight)
    __syncthreads();

    // cD2 has arrived by now; commit with zero stall (sC unread until L2).
    commit(sC, pC, tid);

    // Level 1 (d=4, OFF=16): produce R1 (origin S-16), pairs 8t..8t+7 -> sD
    if (tid < 130) {
        u64 acc[8];
#pragma unroll
        for (int k = 0; k < 8; ++k) acc[k] = 0ULL;
        pass_even<4, 16, 21>(sA, acc, CL2, tid);
        pass_even<4, 16, 21>(sB, acc, CH2, tid);
        u64* p = sD + tid;
#pragma unroll
        for (int k = 0; k < 8; ++k) p[k * W2] = acc[k];
    }
    __syncthreads();

    // All L1 reads of sA done -> commit cD1 into sA (data long arrived).
    commit(sA, pE, tid);

    // Level 2 (d=2, OFF=8): R1 + cD2 -> R2 (origin S-8) into sB (cD3 dead)
    if (tid < 129) {
        u64 acc[8];
#pragma unroll
        for (int k = 0; k < 8; ++k) acc[k] = 0ULL;
        pass_even<2, 8, 14>(sD, acc, CL2, tid);
        pass_even<2, 8, 14>(sC, acc, CH2, tid);
        u64* p = sB + tid;
#pragma unroll
        for (int k = 0; k < 8; ++k) p[k * W2] = acc[k];
    }
    __syncthreads();

    // Level 3 (d=1, OFF=8): R2 + cD1 -> global, scalar FFMA-imm
    if (tid < 128) {
        const float CFL[8] = {L0c,L1c,L2c,L3c,L4c,L5c,L6c,L7c};
        const float CFH[8] = {H0c,H1c,H2c,H3c,H4c,H5c,H6c,H7c};
        float acc[C];
#pragma unroll
        for (int j = 0; j < C; ++j) acc[j] = 0.0f;
        pass_d1(sB, acc, CFL, tid);
        pass_d1(sA, acc, CFH, tid);
        float4* o = (float4*)(out + (size_t)bn * T + S + tid * C);
#pragma unroll
        for (int q = 0; q < 4; ++q)
            o[q] = make_float4(acc[4 * q + 0], acc[4 * q + 1],
                               acc[4 * q + 2], acc[4 * q + 3]);
    }
}

extern "C" void kernel_launch(void* const* d_in, const int* in_sizes, int n_in,
                              void* d_out, int out_size) {
    const float* x = (const float*)d_in[0];
    float* out = (float*)d_out;
    iswt_kernel<<<4096, NTH>>>(x, out);
}